// round 15
// baseline (speedup 1.0000x reference)
#include <cuda_runtime.h>

#define VOCAB 500
#define EMB   64
#define HID   64
#define BATCH 512
#define SEQ   512

// Precomputed input projection: E'[v][i] = b_ih0[i] + sum_j emb[v][j]*W_ih0[i][j]
__device__ float g_xproj[VOCAB * HID];

typedef unsigned long long u64;

__device__ __forceinline__ void fma2(u64 &d, u64 a, u64 b) {
    asm("fma.rn.f32x2 %0, %1, %2, %0;" : "+l"(d) : "l"(a), "l"(b));
}
__device__ __forceinline__ u64 add2(u64 a, u64 b) {
    u64 r; asm("add.rn.f32x2 %0, %1, %2;" : "=l"(r) : "l"(a), "l"(b)); return r;
}
__device__ __forceinline__ float hsum1(u64 a) {
    float lo, hi;
    asm("mov.b64 {%0,%1}, %2;" : "=f"(lo), "=f"(hi) : "l"(a));
    return lo + hi;
}
// HW tanh: MUFU.TANH, ~16 cyc, rel err ~2^-11
__device__ __forceinline__ float fast_tanh(float x) {
    float r;
    asm("tanh.approx.f32 %0, %1;" : "=f"(r) : "f"(x));
    return r;
}

// ---------------------------------------------------------------------------
// Kernel 1: fold embedding + layer-0 input projection into a 500x64 LUT.
// ---------------------------------------------------------------------------
__global__ void xproj_kernel(const float* __restrict__ emb,
                             const float* __restrict__ W_ih0,
                             const float* __restrict__ b_ih0) {
    __shared__ float se[EMB];
    const int v = blockIdx.x;
    const int i = threadIdx.x;
    se[i] = emb[v * EMB + i];
    __syncthreads();
    float acc = 0.0f;
    const float4* wr = (const float4*)(W_ih0 + i * EMB);
    #pragma unroll
    for (int q = 0; q < 16; q++) {
        float4 wv = __ldg(wr + q);
        acc += wv.x * se[4*q+0] + wv.y * se[4*q+1] + wv.z * se[4*q+2] + wv.w * se[4*q+3];
    }
    g_xproj[v * HID + i] = acc + b_ih0[i];
}

// ---------------------------------------------------------------------------
// Kernel 2: sequential scan, QUARTER-SPLIT. CTA = 128 threads = 1 batch row;
// grid = 512; __launch_bounds__(128,4) caps regs at 128 -> 4 CTAs/SM = 16
// warps/SM in 4 independent sync domains (double R14's latency hiding; the
// fma-pipe floor, set by banking rt=3 for f32x2, is unchanged at 576
// cyc/step/SMSP on 4-row SMs).
// Thread (w = tid>>5, L = tid&31): jh = w&1 (j-half), ih = w>>1 (i-half);
// computes row i_c = ih*32+L over its j-half -> weights 3 x 32 floats = 96
// regs (vs 192 in R14). u-chain FUSES Wih1.h1 + Whh1.h2 into one
// accumulator pair (4 accum u64 total).
// Per step: matvec region -> STS (q,u) partials -> bar -> finish (every
// lane pair redundantly computes tanh for i_f = tid>>1; even lanes
// republish h) -> bar. Both h races (read-before-overwrite, write-before-
// read) and the spart race are each separated by one of the two bars; no
// parity buffers needed.
// Index dtype (int64/int32) detected from the global first 128 words.
// ---------------------------------------------------------------------------
__global__ void __launch_bounds__(128, 4)
scan_kernel(const int* __restrict__ xw,
            const float* __restrict__ W_hh0,
            const float* __restrict__ b_hh0,
            const float* __restrict__ W_ih1,
            const float* __restrict__ W_hh1,
            const float* __restrict__ b_ih1,
            const float* __restrict__ b_hh1,
            const float* __restrict__ fc_w,
            const float* __restrict__ fc_b,
            float* __restrict__ out) {
    __shared__ __align__(16) float  sh1[HID];
    __shared__ __align__(16) float  sh2[HID];
    __shared__ float2 spart[2][HID];     // [jhalf][i] = (q, u)
    __shared__ int    sidx[SEQ];
    __shared__ float  swsum[4];
    __shared__ int    s_is64;

    const int tid  = threadIdx.x;
    const int w    = tid >> 5;
    const int L    = tid & 31;
    const int jh   = w & 1;              // j-half for the matvec
    const int ih   = w >> 1;             // i-half for the matvec
    const int i_c  = ih * 32 + L;        // computed row (weights)
    const int i_f  = tid >> 1;           // finished row (lane pairs, redundant)
    const int b    = blockIdx.x;

    // --- weights: row i_c, own j-half, f32x2 pairs (3 x 16 u64 = 96 regs) ---
    u64 w0[16], w1[16], w2[16];          // W_hh0, W_ih1, W_hh1
    {
        const int jbase = jh * 32;
        const u64* q0 = (const u64*)(W_hh0 + i_c * HID + jbase);
        const u64* q1 = (const u64*)(W_ih1 + i_c * HID + jbase);
        const u64* q2 = (const u64*)(W_hh1 + i_c * HID + jbase);
        #pragma unroll
        for (int q = 0; q < 16; q++) {
            w0[q] = __ldg(q0 + q);
            w1[q] = __ldg(q1 + q);
            w2[q] = __ldg(q2 + q);
        }
    }
    const float b1f = b_hh0[i_f];
    const float b2f = b_ih1[i_f] + b_hh1[i_f];

    // --- dtype probe on GLOBAL first 128 words (valid for either layout) ---
    if (tid == 0) {
        int z = 0;
        #pragma unroll
        for (int k = 1; k < 128; k += 2) z |= xw[k];
        s_is64 = (z == 0);
    }
    __syncthreads();
    {
        const int is64 = s_is64;
        const int base = b * SEQ;
        #pragma unroll
        for (int k = tid; k < SEQ; k += 128) {
            int v = is64 ? xw[2 * (base + k)] : xw[base + k];
            sidx[k] = min(max(v, 0), VOCAB - 1);
        }
    }
    __syncthreads();                     // sidx visible

    // prologue: h1_0 = tanh(x_0 + b1), h2_{-1} = 0 (even lanes publish)
    {
        const float x0 = __ldg(&g_xproj[sidx[0] * HID + i_f]);
        if ((tid & 1) == 0) {
            sh1[i_f] = fast_tanh(x0 + b1f);
            sh2[i_f] = 0.0f;
        }
    }
    float xn  = __ldg(&g_xproj[sidx[1] * HID + i_f]);   // x_1
    float h2n = 0.0f;
    __syncthreads();

    const ulonglong2* H1 = (const ulonglong2*)(sh1 + jh * 32);
    const ulonglong2* H2 = (const ulonglong2*)(sh2 + jh * 32);

    #pragma unroll 1
    for (int t = 0; t < SEQ; t++) {
        // matvec over own j-half: q = Whh0.h1_t; u = Wih1.h1_t + Whh1.h2_{t-1}
        u64 q0 = 0, q1 = 0, u0 = 0, u1 = 0;
        #pragma unroll
        for (int m = 0; m < 8; m++) {
            ulonglong2 ha = H1[m];
            fma2(q0, w0[2*m],   ha.x);
            fma2(q1, w0[2*m+1], ha.y);
            fma2(u0, w1[2*m],   ha.x);
            fma2(u1, w1[2*m+1], ha.y);
            ulonglong2 ga = H2[m];
            fma2(u0, w2[2*m],   ga.x);
            fma2(u1, w2[2*m+1], ga.y);
        }
        spart[jh][i_c] = make_float2(hsum1(add2(q0, q1)), hsum1(add2(u0, u1)));
        __syncthreads();                 // B1: partials ready; h reads done

        const int tn = (t + 2 < SEQ) ? (t + 2) : (SEQ - 1);
        const float xc = xn;             // x_{t+1}
        xn = __ldg(&g_xproj[sidx[tn] * HID + i_f]);     // prefetch x_{t+2}

        // finish i_f (lane pairs redundant; even lanes republish)
        const float2 e0 = spart[0][i_f];
        const float2 e1 = spart[1][i_f];
        const float h1n = fast_tanh(e0.x + e1.x + xc + b1f);  // h1_{t+1}
        h2n             = fast_tanh(e0.y + e1.y + b2f);       // h2_t
        if ((tid & 1) == 0) {
            sh1[i_f] = h1n;
            sh2[i_f] = h2n;
        }
        __syncthreads();                 // B2: h republished; spart readable
    }

    // --- final projection: out[b] = fc_w . h2 + fc_b (even lanes carry h2) ---
    const float fw = __ldg(&fc_w[i_f]);
    float val = ((tid & 1) == 0) ? fw * h2n : 0.0f;
    #pragma unroll
    for (int off = 16; off; off >>= 1)
        val += __shfl_xor_sync(0xffffffffu, val, off);
    if (L == 0) swsum[w] = val;
    __syncthreads();
    if (tid == 0) out[b] = swsum[0] + swsum[1] + swsum[2] + swsum[3] + fc_b[0];
}

// ---------------------------------------------------------------------------
extern "C" void kernel_launch(void* const* d_in, const int* in_sizes, int n_in,
                              void* d_out, int out_size) {
    const int*   x_raw = (const int*)d_in[0];
    const float* emb   = (const float*)d_in[1];
    const float* W_ih0 = (const float*)d_in[2];
    const float* W_hh0 = (const float*)d_in[3];
    const float* b_ih0 = (const float*)d_in[4];
    const float* b_hh0 = (const float*)d_in[5];
    const float* W_ih1 = (const float*)d_in[6];
    const float* W_hh1 = (const float*)d_in[7];
    const float* b_ih1 = (const float*)d_in[8];
    const float* b_hh1 = (const float*)d_in[9];
    const float* fc_w  = (const float*)d_in[10];
    const float* fc_b  = (const float*)d_in[11];
    float*       out   = (float*)d_out;

    xproj_kernel<<<VOCAB, HID>>>(emb, W_ih0, b_ih0);
    scan_kernel<<<BATCH, 128>>>(
        x_raw, W_hh0, b_hh0, W_ih1, W_hh1, b_ih1, b_hh1, fc_w, fc_b, out);
}

// round 16
// speedup vs baseline: 1.2193x; 1.2193x over previous
#include <cuda_runtime.h>

#define VOCAB 500
#define EMB   64
#define HID   64
#define BATCH 512
#define SEQ   512

// Precomputed input projection: E'[v][i] = b_ih0[i] + sum_j emb[v][j]*W_ih0[i][j]
__device__ float g_xproj[VOCAB * HID];

typedef unsigned long long u64;

__device__ __forceinline__ void fma2(u64 &d, u64 a, u64 b) {
    asm("fma.rn.f32x2 %0, %1, %2, %0;" : "+l"(d) : "l"(a), "l"(b));
}
__device__ __forceinline__ u64 add2(u64 a, u64 b) {
    u64 r; asm("add.rn.f32x2 %0, %1, %2;" : "=l"(r) : "l"(a), "l"(b)); return r;
}
__device__ __forceinline__ float hsum1(u64 a) {
    float lo, hi;
    asm("mov.b64 {%0,%1}, %2;" : "=f"(lo), "=f"(hi) : "l"(a));
    return lo + hi;
}
// HW tanh: MUFU.TANH, ~16 cyc, rel err ~2^-11
__device__ __forceinline__ float fast_tanh(float x) {
    float r;
    asm("tanh.approx.f32 %0, %1;" : "=f"(r) : "f"(x));
    return r;
}

// ---------------------------------------------------------------------------
// Kernel 1: fold embedding + layer-0 input projection into a 500x64 LUT.
// ---------------------------------------------------------------------------
__global__ void xproj_kernel(const float* __restrict__ emb,
                             const float* __restrict__ W_ih0,
                             const float* __restrict__ b_ih0) {
    __shared__ float se[EMB];
    const int v = blockIdx.x;
    const int i = threadIdx.x;
    se[i] = emb[v * EMB + i];
    __syncthreads();
    float acc = 0.0f;
    const float4* wr = (const float4*)(W_ih0 + i * EMB);
    #pragma unroll
    for (int q = 0; q < 16; q++) {
        float4 wv = __ldg(wr + q);
        acc += wv.x * se[4*q+0] + wv.y * se[4*q+1] + wv.z * se[4*q+2] + wv.w * se[4*q+3];
    }
    g_xproj[v * HID + i] = acc + b_ih0[i];
}

// ---------------------------------------------------------------------------
// Kernel 2: sequential scan, HALF-J OWNERSHIP with register-resident own
// partials. CTA = 64 threads = 1 batch row; grid = 512; 252 regs -> 4
// CTAs/SM (the measured-feasible optimum: 96-reg/128-cap variants spill).
// Thread (w,L): computes rows i0=L and i1=L+32 over j-half [32w,32w+32),
// and finishes row ifin = 32w+L — which is i0 for w=0 and i1 for w=1, so
// the OWN-half partial stays in registers; only the PARTNER half's partial
// crosses smem. spart traffic is halved vs R14: warp w stores only the two
// floats warp w^1 needs (spart[p][w][L]) and loads only spart[p][w^1][L].
// Per step: 96-fma2 matvec (q = Whh0.h1_t per row; u = Wih1.h1_t +
// Whh1.h2_{t-1} fused) -> STS partner partial -> __syncthreads -> finish
// (own-reg + partner partial, two MUFU.TANH, pipelined h1_{t+1}) ->
// republish h into OWN j-half (intra-warp) -> __syncwarp.
// spart parity race-free: read(t) precedes the reader's bar(t+1) arrival;
// the slot's next write (t+2) follows bar(t+1).
// Index dtype (int64/int32) detected from the global first 128 words.
// ---------------------------------------------------------------------------
__global__ void __launch_bounds__(64, 4)
scan_kernel(const int* __restrict__ xw,
            const float* __restrict__ W_hh0,
            const float* __restrict__ b_hh0,
            const float* __restrict__ W_ih1,
            const float* __restrict__ W_hh1,
            const float* __restrict__ b_ih1,
            const float* __restrict__ b_hh1,
            const float* __restrict__ fc_w,
            const float* __restrict__ fc_b,
            float* __restrict__ out) {
    __shared__ __align__(16) float  sh1[HID];      // single-buffered h1
    __shared__ __align__(16) float  sh2[HID];      // single-buffered h2
    __shared__ float2 spart[2][2][32];             // [parity][srcwarp][L] = (q,u)
    __shared__ int    sidx[SEQ];
    __shared__ float  swsum[2];
    __shared__ int    s_is64;

    const int tid  = threadIdx.x;
    const int w    = tid >> 5;           // j-half / finish-half
    const int L    = tid & 31;
    const int i0   = L;                  // computed rows (weights)
    const int i1   = L + 32;
    const int ifin = w * 32 + L;         // finished output row
    const int jbase = w * 32;
    const int b    = blockIdx.x;

    // --- weights: rows i0,i1 x own j-half, f32x2 pairs (96 u64 = 192 regs) ---
    u64 w00[16], w01[16], w10[16], w11[16], w20[16], w21[16];
    {
        const u64* p00 = (const u64*)(W_hh0 + i0 * HID + jbase);
        const u64* p01 = (const u64*)(W_hh0 + i1 * HID + jbase);
        const u64* p10 = (const u64*)(W_ih1 + i0 * HID + jbase);
        const u64* p11 = (const u64*)(W_ih1 + i1 * HID + jbase);
        const u64* p20 = (const u64*)(W_hh1 + i0 * HID + jbase);
        const u64* p21 = (const u64*)(W_hh1 + i1 * HID + jbase);
        #pragma unroll
        for (int q = 0; q < 16; q++) {
            w00[q] = __ldg(p00 + q);  w01[q] = __ldg(p01 + q);
            w10[q] = __ldg(p10 + q);  w11[q] = __ldg(p11 + q);
            w20[q] = __ldg(p20 + q);  w21[q] = __ldg(p21 + q);
        }
    }
    const float b1f = b_hh0[ifin];
    const float b2f = b_ih1[ifin] + b_hh1[ifin];

    // --- dtype probe on GLOBAL first 128 words (valid for either layout) ---
    if (tid == 0) {
        int z = 0;
        #pragma unroll
        for (int k = 1; k < 128; k += 2) z |= xw[k];
        s_is64 = (z == 0);
    }
    __syncthreads();
    {
        const int is64 = s_is64;
        const int base = b * SEQ;
        #pragma unroll
        for (int k = tid; k < SEQ; k += 64) {
            int v = is64 ? xw[2 * (base + k)] : xw[base + k];
            sidx[k] = min(max(v, 0), VOCAB - 1);
        }
    }
    __syncthreads();                      // sidx visible to both warps

    // prologue: h1_0 = tanh(x_0 + b1), h2_{-1} = 0, published into OWN half
    sh1[ifin] = fast_tanh(__ldg(&g_xproj[sidx[0] * HID + ifin]) + b1f);
    sh2[ifin] = 0.0f;
    __syncwarp();                         // intra-warp h visibility

    const ulonglong2* H1 = (const ulonglong2*)(sh1 + jbase);
    const ulonglong2* H2 = (const ulonglong2*)(sh2 + jbase);

    float xn  = __ldg(&g_xproj[sidx[1] * HID + ifin]);   // x_1
    float h2n = 0.0f;

    #pragma unroll 1
    for (int t = 0; t < SEQ; t++) {
        const int p = t & 1;

        // matvec over own j-half: q per row; u = Wih1.h1 + Whh1.h2 fused
        u64 qa = 0, qb = 0, ua0 = 0, ua1 = 0, ub0 = 0, ub1 = 0;
        #pragma unroll
        for (int m = 0; m < 8; m++) {
            ulonglong2 h = H1[m];
            fma2(qa,  w00[2*m], h.x);  fma2(qa,  w00[2*m+1], h.y);
            fma2(qb,  w01[2*m], h.x);  fma2(qb,  w01[2*m+1], h.y);
            fma2(ua0, w10[2*m], h.x);  fma2(ua1, w10[2*m+1], h.y);
            fma2(ub0, w11[2*m], h.x);  fma2(ub1, w11[2*m+1], h.y);
            ulonglong2 g = H2[m];
            fma2(ua0, w20[2*m], g.x);  fma2(ua1, w20[2*m+1], g.y);
            fma2(ub0, w21[2*m], g.x);  fma2(ub1, w21[2*m+1], g.y);
        }
        const float fq0 = hsum1(qa);
        const float fq1 = hsum1(qb);
        const float fu0 = hsum1(add2(ua0, ua1));
        const float fu1 = hsum1(add2(ub0, ub1));

        // store ONLY what the partner warp needs; keep own partial in regs
        const float q_own = (w == 0) ? fq0 : fq1;
        const float u_own = (w == 0) ? fu0 : fu1;
        spart[p][w][L] = (w == 0) ? make_float2(fq1, fu1)
                                  : make_float2(fq0, fu0);
        __syncthreads();                  // the ONLY CTA barrier in the step

        const int tn = (t + 2 < SEQ) ? (t + 2) : (SEQ - 1);
        const float xc = xn;              // x_{t+1}
        xn = __ldg(&g_xproj[sidx[tn] * HID + ifin]);     // prefetch x_{t+2}

        // finish own row: own-reg partial + partner partial from smem
        const float2 eo = spart[p][w ^ 1][L];
        const float h1n = fast_tanh(q_own + eo.x + xc + b1f);  // h1_{t+1}
        h2n             = fast_tanh(u_own + eo.y + b2f);       // h2_t
        sh1[ifin] = h1n;
        sh2[ifin] = h2n;
        __syncwarp();                     // intra-warp republish ordering
    }

    // --- final projection: out[b] = fc_w . h2 + fc_b ---
    float val = __ldg(&fc_w[ifin]) * h2n;
    #pragma unroll
    for (int off = 16; off; off >>= 1)
        val += __shfl_xor_sync(0xffffffffu, val, off);
    if (L == 0) swsum[w] = val;
    __syncthreads();
    if (tid == 0) out[b] = swsum[0] + swsum[1] + fc_b[0];
}

// ---------------------------------------------------------------------------
extern "C" void kernel_launch(void* const* d_in, const int* in_sizes, int n_in,
                              void* d_out, int out_size) {
    const int*   x_raw = (const int*)d_in[0];
    const float* emb   = (const float*)d_in[1];
    const float* W_ih0 = (const float*)d_in[2];
    const float* W_hh0 = (const float*)d_in[3];
    const float* b_ih0 = (const float*)d_in[4];
    const float* b_hh0 = (const float*)d_in[5];
    const float* W_ih1 = (const float*)d_in[6];
    const float* W_hh1 = (const float*)d_in[7];
    const float* b_ih1 = (const float*)d_in[8];
    const float* b_hh1 = (const float*)d_in[9];
    const float* fc_w  = (const float*)d_in[10];
    const float* fc_b  = (const float*)d_in[11];
    float*       out   = (float*)d_out;

    xproj_kernel<<<VOCAB, HID>>>(emb, W_ih0, b_ih0);
    scan_kernel<<<BATCH, 64>>>(
        x_raw, W_hh0, b_hh0, W_ih1, W_hh1, b_ih1, b_hh1, fc_w, fc_b, out);
}